// round 3
// baseline (speedup 1.0000x reference)
#include <cuda_runtime.h>
#include <math.h>
#include <stdint.h>

// ---------------- problem constants ----------------
#define BATCH   4096
#define NBLOCK  100
#define NSLOT   300
#define NYS     1236
#define HIDDIM  256
#define NSTEPS  100
#define KST     1436        // 100 + 100 + 1236
#define M5      (BATCH*5)
#define GDIM    (4*HIDDIM)  // 1024
#define NFUSE   (NBLOCK+NSLOT) // 400
#define NEGV    (-1000.0f)

// ---------------- scratch (device globals; no allocs allowed) ----------------
__device__ float g_xT  [(size_t)M5 * KST];      // transposed state, MLP input
__device__ float g_act1[(size_t)M5 * 512];
__device__ float g_act2[(size_t)M5 * 512];
__device__ float g_act3[(size_t)M5 * 256];
__device__ float g_h_to[BATCH*HIDDIM];
__device__ float g_c_to[BATCH*HIDDIM];
__device__ float g_h_ti[BATCH*HIDDIM];
__device__ float g_c_ti[BATCH*HIDDIM];
__device__ float g_gto [(size_t)BATCH*GDIM];
__device__ float g_gti [(size_t)BATCH*GDIM];
__device__ float g_lto [(size_t)BATCH*NFUSE];
__device__ float g_lti [(size_t)BATCH*NBLOCK];
__device__ float g_inp [BATCH*8];
__device__ unsigned char g_mto[BATCH*NBLOCK];
__device__ unsigned char g_mti[BATCH*NBLOCK];
__device__ float g_slots[(size_t)BATCH*NSLOT*5];
__device__ float g_WbWs[NFUSE*HIDDIM];
__device__ float g_bf  [NFUSE];

// ---------------- XLA-GPU-faithful transcendentals ----------------
// XLA GpuElementalIrEmitter::EmitTanh: |x| >= 20 -> copysign(1,x), else
// llvm_ir::EmitFastTanh: |x| < 0.0004 -> x, else rational approx on
// x clamped to +/-7.90531110763549805, plain FMul/FAdd (no fma contraction).
__device__ __forceinline__ float xla_tanh(float x) {
    float ax = fabsf(x);
    float xc = fminf(fmaxf(x, -7.90531110763549805f), 7.90531110763549805f);
    float x2 = __fmul_rn(xc, xc);
    float p = -2.76076847742355e-16f;
    p = __fadd_rn(__fmul_rn(x2, p),  2.00018790482477e-13f);
    p = __fadd_rn(__fmul_rn(x2, p), -8.60467152213735e-11f);
    p = __fadd_rn(__fmul_rn(x2, p),  5.12229709037114e-08f);
    p = __fadd_rn(__fmul_rn(x2, p),  1.48572235717979e-05f);
    p = __fadd_rn(__fmul_rn(x2, p),  6.37261928875436e-04f);
    p = __fadd_rn(__fmul_rn(x2, p),  4.89352455891786e-03f);
    float num = __fmul_rn(xc, p);
    float q = 1.19825839466702e-06f;
    q = __fadd_rn(__fmul_rn(x2, q), 1.18534705686654e-04f);
    q = __fadd_rn(__fmul_rn(x2, q), 2.26843463243900e-03f);
    q = __fadd_rn(__fmul_rn(x2, q), 4.89352518554385e-03f);
    float r = __fdiv_rn(num, q);
    r = (ax < 0.0004f) ? x : r;
    r = (ax < 20.0f) ? r : copysignf(1.0f, x);
    return r;
}

// XLA LogisticExpander: logistic(x) = 1 / (1 + exp(-x)), exp -> __nv_expf (== expf)
__device__ __forceinline__ float xla_sigm(float x) {
    return __fdiv_rn(1.0f, __fadd_rn(1.0f, expf(-x)));
}

// ---------------- prep: state copy to output + transposed MLP input ----------------
__global__ void prep_kernel(const float* __restrict__ to_t, const float* __restrict__ ti_t,
                            const float* __restrict__ ys_t, float* __restrict__ out_state)
{
    int idx = blockIdx.x * blockDim.x + threadIdx.x;
    if (idx >= BATCH * KST) return;
    int b = idx / KST, i = idx - b * KST;
    const float* src;
    if (i < NBLOCK)            src = to_t + ((size_t)b * NBLOCK + i) * 5;
    else if (i < 2 * NBLOCK)   src = ti_t + ((size_t)b * NBLOCK + (i - NBLOCK)) * 5;
    else                       src = ys_t + ((size_t)b * NYS + (i - 2 * NBLOCK)) * 5;
#pragma unroll
    for (int r = 0; r < 5; r++) {
        float v = src[r];
        out_state[(size_t)idx * 5 + r] = v;
        g_xT[(size_t)(b * 5 + r) * KST + i] = v;
    }
}

// ---------------- build fused [Wb;Ws] logits weight ----------------
__global__ void wbws_kernel(const float* __restrict__ Wb, const float* __restrict__ bb,
                            const float* __restrict__ Ws, const float* __restrict__ bs)
{
    int i = blockIdx.x, j = threadIdx.x;
    g_WbWs[i * HIDDIM + j] = (i < NBLOCK) ? Wb[i * HIDDIM + j] : Ws[(i - NBLOCK) * HIDDIM + j];
    if (j == 0) g_bf[i] = (i < NBLOCK) ? bb[i] : bs[i - NBLOCK];
}

// ---------------- fp32 GEMM: C[M,N] = A[M,K] @ B[N,K]^T (+bias, relu) ----------------
// Single accumulator per output, k ascending, FFMA -> bitwise == cuBLAS SGEMM.
__global__ void __launch_bounds__(256, 2) sgemm_nt(
    const float* __restrict__ A, int lda,
    const float* __restrict__ Bm, int ldb,
    const float* __restrict__ bias,
    float* __restrict__ C, int ldc,
    int M, int N, int K, int relu)
{
    __shared__ float As[16][132];
    __shared__ float Bs[16][132];
    const int m0 = blockIdx.x * 128, n0 = blockIdx.y * 128;
    const int tid = threadIdx.x;
    const int tx = tid & 15, ty = tid >> 4;
    float acc[8][8];
#pragma unroll
    for (int i = 0; i < 8; i++)
#pragma unroll
        for (int j = 0; j < 8; j++) acc[i][j] = 0.f;

    for (int k0 = 0; k0 < K; k0 += 16) {
#pragma unroll
        for (int e = 0; e < 8; e++) {
            int idx = tid + e * 256;
            int m = idx >> 4, kk = idx & 15;
            float va = 0.f, vb = 0.f;
            if (k0 + kk < K)                 va = A[(size_t)(m0 + m) * lda + k0 + kk];
            if (k0 + kk < K && n0 + m < N)   vb = Bm[(size_t)(n0 + m) * ldb + k0 + kk];
            As[kk][m] = va;
            Bs[kk][m] = vb;
        }
        __syncthreads();
#pragma unroll
        for (int kk = 0; kk < 16; kk++) {
            float a[8], bv[8];
#pragma unroll
            for (int i = 0; i < 4; i++) {
                a[i]      = As[kk][ty * 4 + i];
                a[4 + i]  = As[kk][64 + ty * 4 + i];
                bv[i]     = Bs[kk][tx * 4 + i];
                bv[4 + i] = Bs[kk][64 + tx * 4 + i];
            }
#pragma unroll
            for (int i = 0; i < 8; i++)
#pragma unroll
                for (int j = 0; j < 8; j++)
                    acc[i][j] = __fmaf_rn(a[i], bv[j], acc[i][j]);
        }
        __syncthreads();
    }
#pragma unroll
    for (int i = 0; i < 8; i++) {
        int m = m0 + ((i < 4) ? (ty * 4 + i) : (64 + ty * 4 + i - 4));
#pragma unroll
        for (int j = 0; j < 8; j++) {
            int n = n0 + ((j < 4) ? (tx * 4 + j) : (64 + tx * 4 + j - 4));
            if (n < N) {
                float v = acc[i][j];
                if (bias) v = __fadd_rn(v, bias[n]);
                if (relu) v = fmaxf(v, 0.f);
                C[(size_t)m * ldc + n] = v;
            }
        }
    }
}

// ---------------- feat_vec + carry init ----------------
__global__ void feat_init_kernel(const float* __restrict__ W_fe2, const float* __restrict__ b_fe2,
                                 const float* __restrict__ to_t, const float* __restrict__ ti_t,
                                 const float* __restrict__ slot_info)
{
    int b = blockIdx.x, j = threadIdx.x;
    // sequential ascending fma from 0 (cuBLAS order), bias added after
    float f = 0.f;
#pragma unroll
    for (int r = 0; r < 5; r++)
        f = __fmaf_rn(g_act3[(size_t)(b * 5 + r) * HIDDIM + j], W_fe2[r], f);
    f = __fadd_rn(f, b_fe2[0]);
    g_h_to[b * HIDDIM + j] = f;
    g_h_ti[b * HIDDIM + j] = f;
    g_c_to[b * HIDDIM + j] = 0.f;
    g_c_ti[b * HIDDIM + j] = 0.f;
    if (j < 8) g_inp[b * 8 + j] = 0.f;
    if (j < NBLOCK) {
        g_mto[b * NBLOCK + j] = (to_t[((size_t)b * NBLOCK + j) * 5] != -1.0f);
        g_mti[b * NBLOCK + j] = (ti_t[((size_t)b * NBLOCK + j) * 5] != -1.0f);
    }
    for (int t = j; t < NSLOT * 5; t += HIDDIM)
        g_slots[(size_t)b * NSLOT * 5 + t] = slot_info[(size_t)b * NSLOT * 5 + t];
}

// ---------------- LSTM cell update (both cells), strict IEEE rn ordering ----------------
__device__ __forceinline__ float dot5_fma(const float* s, const float* w) {
    float a = 0.f;
    a = __fmaf_rn(s[0], w[0], a);
    a = __fmaf_rn(s[1], w[1], a);
    a = __fmaf_rn(s[2], w[2], a);
    a = __fmaf_rn(s[3], w[3], a);
    a = __fmaf_rn(s[4], w[4], a);
    return a;
}

__global__ void cell_kernel(const float* __restrict__ bih_to, const float* __restrict__ bhh_to,
                            const float* __restrict__ Wih_to,
                            const float* __restrict__ bih_ti, const float* __restrict__ bhh_ti)
{
    int b = blockIdx.x, j = threadIdx.x;
    __shared__ float sin5[5];
    if (j < 5) sin5[j] = g_inp[b * 8 + j];
    __syncthreads();

    const float* g = g_gto + (size_t)b * GDIM;
    // reference order: ((x@Wih.T + bih) + h@Whh.T) + bhh
    float gi = __fadd_rn(__fadd_rn(__fadd_rn(dot5_fma(sin5, Wih_to + (size_t)(j)       * 5), bih_to[j]),       g[j]),       bhh_to[j]);
    float gf = __fadd_rn(__fadd_rn(__fadd_rn(dot5_fma(sin5, Wih_to + (size_t)(256 + j) * 5), bih_to[256 + j]), g[256 + j]), bhh_to[256 + j]);
    float gg = __fadd_rn(__fadd_rn(__fadd_rn(dot5_fma(sin5, Wih_to + (size_t)(512 + j) * 5), bih_to[512 + j]), g[512 + j]), bhh_to[512 + j]);
    float go = __fadd_rn(__fadd_rn(__fadd_rn(dot5_fma(sin5, Wih_to + (size_t)(768 + j) * 5), bih_to[768 + j]), g[768 + j]), bhh_to[768 + j]);
    // c = sig(f)*c + sig(i)*tanh(g)  -- separate mul/mul/add (no contraction)
    float m1 = __fmul_rn(xla_sigm(gf), g_c_to[b * HIDDIM + j]);
    float m2 = __fmul_rn(xla_sigm(gi), xla_tanh(gg));
    float c  = __fadd_rn(m1, m2);
    g_c_to[b * HIDDIM + j] = c;
    g_h_to[b * HIDDIM + j] = __fmul_rn(xla_sigm(go), xla_tanh(c));

    const float* g2 = g_gti + (size_t)b * GDIM;   // ti-LSTM input is zeros -> x@Wih.T == +0
    float ti_i = __fadd_rn(__fadd_rn(__fadd_rn(0.f, bih_ti[j]),       g2[j]),       bhh_ti[j]);
    float ti_f = __fadd_rn(__fadd_rn(__fadd_rn(0.f, bih_ti[256 + j]), g2[256 + j]), bhh_ti[256 + j]);
    float ti_g = __fadd_rn(__fadd_rn(__fadd_rn(0.f, bih_ti[512 + j]), g2[512 + j]), bhh_ti[512 + j]);
    float ti_o = __fadd_rn(__fadd_rn(__fadd_rn(0.f, bih_ti[768 + j]), g2[768 + j]), bhh_ti[768 + j]);
    float n1 = __fmul_rn(xla_sigm(ti_f), g_c_ti[b * HIDDIM + j]);
    float n2 = __fmul_rn(xla_sigm(ti_i), xla_tanh(ti_g));
    float c2 = __fadd_rn(n1, n2);
    g_c_ti[b * HIDDIM + j] = c2;
    g_h_ti[b * HIDDIM + j] = __fmul_rn(xla_sigm(ti_o), xla_tanh(c2));
}

// ---------------- masked argmax + state mutation + action write ----------------
__global__ void select_kernel(const float* __restrict__ to_t, float* __restrict__ out_act, int step)
{
    int b = blockIdx.x, tid = threadIdx.x;
    __shared__ float sv[128];
    __shared__ int   si[128];
    __shared__ float sinp[5];
    __shared__ int   ssel[2];

    // ---- phase 1: block argmax (h_to) ----
    float v = -3.4e38f; int bi = 0x7fffffff;
    if (tid < NBLOCK) {
        v = g_mto[b * NBLOCK + tid] ? g_lto[(size_t)b * NFUSE + tid] : NEGV;
        bi = tid;
    }
    sv[tid] = v; si[tid] = bi; __syncthreads();
    for (int s = 64; s > 0; s >>= 1) {
        if (tid < s) {
            float v2 = sv[tid + s]; int i2 = si[tid + s];
            if (v2 > sv[tid] || (v2 == sv[tid] && i2 < si[tid])) { sv[tid] = v2; si[tid] = i2; }
        }
        __syncthreads();
    }
    if (tid == 0) {
        int sel = si[0]; ssel[0] = sel;
        g_mto[b * NBLOCK + sel] = 0;
#pragma unroll
        for (int r = 0; r < 5; r++) {
            float x = to_t[((size_t)b * NBLOCK + sel) * 5 + r];
            sinp[r] = x;
            g_inp[b * 8 + r] = x;
        }
    }
    __syncthreads();

    // ---- phase 2: slot argmax ----
    float bl0 = sinp[0], bl1 = sinp[1];
    v = -3.4e38f; bi = 0x7fffffff;
    for (int i = tid; i < NSLOT; i += 128) {
        const float* sl = g_slots + ((size_t)b * NSLOT + i) * 5;
        float l0 = sl[0], w0 = sl[1];
        bool bad = (bl0 >= l0) || (bl1 >= w0) || (l0 == 0.0f);
        float lv = bad ? NEGV : g_lto[(size_t)b * NFUSE + NBLOCK + i];
        if (lv > v || (lv == v && i < bi)) { v = lv; bi = i; }
    }
    sv[tid] = v; si[tid] = bi; __syncthreads();
    for (int s = 64; s > 0; s >>= 1) {
        if (tid < s) {
            float v2 = sv[tid + s]; int i2 = si[tid + s];
            if (v2 > sv[tid] || (v2 == sv[tid] && i2 < si[tid])) { sv[tid] = v2; si[tid] = i2; }
        }
        __syncthreads();
    }
    if (tid == 0) {
        int sel = si[0]; ssel[1] = sel;
        float* sl = g_slots + ((size_t)b * NSLOT + sel) * 5;
        float cnt = __fadd_rn(sl[4], -1.0f);
        sl[4] = cnt;
        if (cnt == 0.0f) { sl[0] = 0.f; sl[1] = 0.f; sl[2] = 0.f; sl[3] = 0.f; sl[4] = 0.f; }
    }
    __syncthreads();

    // ---- phase 3: ti block argmax (h_ti) ----
    v = -3.4e38f; bi = 0x7fffffff;
    if (tid < NBLOCK) {
        v = g_mti[b * NBLOCK + tid] ? g_lti[(size_t)b * NBLOCK + tid] : NEGV;
        bi = tid;
    }
    sv[tid] = v; si[tid] = bi; __syncthreads();
    for (int s = 64; s > 0; s >>= 1) {
        if (tid < s) {
            float v2 = sv[tid + s]; int i2 = si[tid + s];
            if (v2 > sv[tid] || (v2 == sv[tid] && i2 < si[tid])) { sv[tid] = v2; si[tid] = i2; }
        }
        __syncthreads();
    }
    if (tid == 0) {
        int sel = si[0];
        g_mti[b * NBLOCK + sel] = 0;
        float* oa = out_act + ((size_t)b * NSTEPS + step) * 3;
        oa[0] = (float)ssel[0];
        oa[1] = (float)ssel[1];
        oa[2] = (float)sel;
    }
}

// ---------------- launch ----------------
extern "C" void kernel_launch(void* const* d_in, const int* in_sizes, int n_in,
                              void* d_out, int out_size)
{
    const float* to_t    = (const float*)d_in[0];
    const float* ti_t    = (const float*)d_in[1];
    const float* ys_t    = (const float*)d_in[2];
    const float* slot    = (const float*)d_in[3];
    const float* W1      = (const float*)d_in[4];
    const float* b1      = (const float*)d_in[5];
    const float* W2      = (const float*)d_in[6];
    const float* b2      = (const float*)d_in[7];
    const float* W3      = (const float*)d_in[8];
    const float* b3      = (const float*)d_in[9];
    const float* W_fe2   = (const float*)d_in[10];
    const float* b_fe2   = (const float*)d_in[11];
    const float* Wih_to  = (const float*)d_in[12];
    const float* Whh_to  = (const float*)d_in[13];
    const float* bih_to  = (const float*)d_in[14];
    const float* bhh_to  = (const float*)d_in[15];
    const float* Whh_ti  = (const float*)d_in[17];
    const float* bih_ti  = (const float*)d_in[18];
    const float* bhh_ti  = (const float*)d_in[19];
    const float* Wb      = (const float*)d_in[20];
    const float* bb      = (const float*)d_in[21];
    const float* Ws      = (const float*)d_in[22];
    const float* bs      = (const float*)d_in[23];

    float* out     = (float*)d_out;
    float* out_act = out + (size_t)BATCH * KST * 5;

    float *p_xT, *p_a1, *p_a2, *p_a3, *p_hto, *p_hti, *p_gto, *p_gti, *p_lto, *p_lti, *p_wbws, *p_bf;
    cudaGetSymbolAddress((void**)&p_xT,   g_xT);
    cudaGetSymbolAddress((void**)&p_a1,   g_act1);
    cudaGetSymbolAddress((void**)&p_a2,   g_act2);
    cudaGetSymbolAddress((void**)&p_a3,   g_act3);
    cudaGetSymbolAddress((void**)&p_hto,  g_h_to);
    cudaGetSymbolAddress((void**)&p_hti,  g_h_ti);
    cudaGetSymbolAddress((void**)&p_gto,  g_gto);
    cudaGetSymbolAddress((void**)&p_gti,  g_gti);
    cudaGetSymbolAddress((void**)&p_lto,  g_lto);
    cudaGetSymbolAddress((void**)&p_lti,  g_lti);
    cudaGetSymbolAddress((void**)&p_wbws, g_WbWs);
    cudaGetSymbolAddress((void**)&p_bf,   g_bf);

    // prep: state copy + transposed MLP input
    int nprep = (BATCH * KST + 255) / 256;
    prep_kernel<<<nprep, 256>>>(to_t, ti_t, ys_t, out);
    wbws_kernel<<<NFUSE, HIDDIM>>>(Wb, bb, Ws, bs);

    // MLP (relu fused, bias fused)
    dim3 g1(M5 / 128, 512 / 128);
    sgemm_nt<<<g1, 256>>>(p_xT, KST, W1, KST, b1, p_a1, 512, M5, 512, KST, 1);
    sgemm_nt<<<g1, 256>>>(p_a1, 512, W2, 512, b2, p_a2, 512, M5, 512, 512, 1);
    dim3 g3(M5 / 128, 256 / 128);
    sgemm_nt<<<g3, 256>>>(p_a2, 512, W3, 512, b3, p_a3, 256, M5, 256, 512, 1);
    feat_init_kernel<<<BATCH, HIDDIM>>>(W_fe2, b_fe2, to_t, ti_t, slot);

    dim3 gg(BATCH / 128, GDIM / 128);
    dim3 gl(BATCH / 128, (NFUSE + 127) / 128);
    dim3 gl2(BATCH / 128, 1);
    for (int s = 0; s < NSTEPS; s++) {
        sgemm_nt<<<gg, 256>>>(p_hto, HIDDIM, Whh_to, HIDDIM, nullptr, p_gto, GDIM, BATCH, GDIM, HIDDIM, 0);
        sgemm_nt<<<gg, 256>>>(p_hti, HIDDIM, Whh_ti, HIDDIM, nullptr, p_gti, GDIM, BATCH, GDIM, HIDDIM, 0);
        cell_kernel<<<BATCH, HIDDIM>>>(bih_to, bhh_to, Wih_to, bih_ti, bhh_ti);
        sgemm_nt<<<gl, 256>>>(p_hto, HIDDIM, p_wbws, HIDDIM, p_bf, p_lto, NFUSE, BATCH, NFUSE, HIDDIM, 0);
        sgemm_nt<<<gl2, 256>>>(p_hti, HIDDIM, Wb, HIDDIM, bb, p_lti, NBLOCK, BATCH, NBLOCK, HIDDIM, 0);
        select_kernel<<<BATCH, 128>>>(to_t, out_act, s);
    }
}

// round 4
// speedup vs baseline: 1.3575x; 1.3575x over previous
#include <cuda_runtime.h>
#include <math.h>
#include <stdint.h>

// ---------------- problem constants ----------------
#define BATCH   4096
#define NBLOCK  100
#define NSLOT   300
#define NYS     1236
#define HIDDIM  256
#define NSTEPS  100
#define KST     1436        // 100 + 100 + 1236
#define M5      (BATCH*5)
#define GDIM    (4*HIDDIM)  // 1024
#define NFUSE   (NBLOCK+NSLOT) // 400
#define NEGV    (-1000.0f)

// ---------------- scratch (device globals; no allocs allowed) ----------------
__device__ float g_xT  [(size_t)M5 * KST];      // transposed state, MLP input
__device__ float g_act1[(size_t)M5 * 512];
__device__ float g_act2[(size_t)M5 * 512];
__device__ float g_act3[(size_t)M5 * 256];
__device__ float g_h_to[2][BATCH*HIDDIM];
__device__ float g_c_to[BATCH*HIDDIM];
__device__ float g_h_ti[2][BATCH*HIDDIM];
__device__ float g_c_ti[BATCH*HIDDIM];
__device__ float g_lto [(size_t)BATCH*NFUSE];
__device__ float g_lti [(size_t)BATCH*NBLOCK];
__device__ float g_inp [BATCH*8];
__device__ unsigned char g_mto[BATCH*NBLOCK];
__device__ unsigned char g_mti[BATCH*NBLOCK];
__device__ float g_slots[(size_t)BATCH*NSLOT*5];
__device__ float g_WbWs[NFUSE*HIDDIM];
__device__ float g_bf  [NFUSE];
// permuted gate weights: row 4j+g (to: rows 0..1023, ti: rows 1024..2047)
__device__ float g_Wg  [2048*HIDDIM];
__device__ float g_bihp[2048];
__device__ float g_bhhp[2048];
__device__ float g_Wihp[1024*5];

// ---------------- packed f32x2 helpers (bitwise == scalar FFMA rn per lane) ----
__device__ __forceinline__ unsigned long long ffma2(unsigned long long a, unsigned long long b, unsigned long long c) {
    unsigned long long d;
    asm("fma.rn.f32x2 %0, %1, %2, %3;" : "=l"(d) : "l"(a), "l"(b), "l"(c));
    return d;
}
__device__ __forceinline__ unsigned long long pack2(float x) {
    unsigned long long d;
    asm("mov.b64 %0, {%1, %1};" : "=l"(d) : "f"(x));
    return d;
}
__device__ __forceinline__ void unpack2(unsigned long long v, float& lo, float& hi) {
    asm("mov.b64 {%0, %1}, %2;" : "=f"(lo), "=f"(hi) : "l"(v));
}

// ---------------- XLA-GPU-faithful transcendentals ----------------
__device__ __forceinline__ float xla_tanh(float x) {
    float ax = fabsf(x);
    float xc = fminf(fmaxf(x, -7.90531110763549805f), 7.90531110763549805f);
    float x2 = __fmul_rn(xc, xc);
    float p = -2.76076847742355e-16f;
    p = __fadd_rn(__fmul_rn(x2, p),  2.00018790482477e-13f);
    p = __fadd_rn(__fmul_rn(x2, p), -8.60467152213735e-11f);
    p = __fadd_rn(__fmul_rn(x2, p),  5.12229709037114e-08f);
    p = __fadd_rn(__fmul_rn(x2, p),  1.48572235717979e-05f);
    p = __fadd_rn(__fmul_rn(x2, p),  6.37261928875436e-04f);
    p = __fadd_rn(__fmul_rn(x2, p),  4.89352455891786e-03f);
    float num = __fmul_rn(xc, p);
    float q = 1.19825839466702e-06f;
    q = __fadd_rn(__fmul_rn(x2, q), 1.18534705686654e-04f);
    q = __fadd_rn(__fmul_rn(x2, q), 2.26843463243900e-03f);
    q = __fadd_rn(__fmul_rn(x2, q), 4.89352518554385e-03f);
    float r = __fdiv_rn(num, q);
    r = (ax < 0.0004f) ? x : r;
    r = (ax < 20.0f) ? r : copysignf(1.0f, x);
    return r;
}
__device__ __forceinline__ float xla_sigm(float x) {
    return __fdiv_rn(1.0f, __fadd_rn(1.0f, expf(-x)));
}

// ---------------- prep: state copy to output + transposed MLP input ----------------
__global__ void prep_kernel(const float* __restrict__ to_t, const float* __restrict__ ti_t,
                            const float* __restrict__ ys_t, float* __restrict__ out_state)
{
    int idx = blockIdx.x * blockDim.x + threadIdx.x;
    if (idx >= BATCH * KST) return;
    int b = idx / KST, i = idx - b * KST;
    const float* src;
    if (i < NBLOCK)            src = to_t + ((size_t)b * NBLOCK + i) * 5;
    else if (i < 2 * NBLOCK)   src = ti_t + ((size_t)b * NBLOCK + (i - NBLOCK)) * 5;
    else                       src = ys_t + ((size_t)b * NYS + (i - 2 * NBLOCK)) * 5;
#pragma unroll
    for (int r = 0; r < 5; r++) {
        float v = src[r];
        out_state[(size_t)idx * 5 + r] = v;
        g_xT[(size_t)(b * 5 + r) * KST + i] = v;
    }
}

// ---------------- weight prep: permuted gate weights + fused logits weight ------
__global__ void prep_weights(const float* __restrict__ Whh_to, const float* __restrict__ Whh_ti,
                             const float* __restrict__ bih_to, const float* __restrict__ bhh_to,
                             const float* __restrict__ bih_ti, const float* __restrict__ bhh_ti,
                             const float* __restrict__ Wih_to,
                             const float* __restrict__ Wb, const float* __restrict__ bb,
                             const float* __restrict__ Ws, const float* __restrict__ bs)
{
    int r = blockIdx.x, j = threadIdx.x;      // r in 0..2047, j in 0..255
    int rr = r & 1023, g = rr & 3, jj = rr >> 2;
    int src = g * 256 + jj;                   // original gate-major row
    g_Wg[r * 256 + j] = (r < 1024) ? Whh_to[src * 256 + j] : Whh_ti[src * 256 + j];
    if (j == 0) {
        g_bihp[r] = (r < 1024) ? bih_to[src] : bih_ti[src];
        g_bhhp[r] = (r < 1024) ? bhh_to[src] : bhh_ti[src];
    }
    if (r < 1024 && j < 5) g_Wihp[r * 5 + j] = Wih_to[src * 5 + j];
    if (r < NFUSE) {
        g_WbWs[r * 256 + j] = (r < NBLOCK) ? Wb[r * 256 + j] : Ws[(r - NBLOCK) * 256 + j];
        if (j == 0) g_bf[r] = (r < NBLOCK) ? bb[r] : bs[r - NBLOCK];
    }
}

// ---------------- FFMA2 GEMM core: C[128,128] tile of A[M,K] @ B[N,K]^T ----------
// k ascending, single accumulator per column, rn per lane -> bitwise == scalar FFMA.
#define SMSTRIDE 2112   // 16*132
__device__ __forceinline__ void gemm_core(
    const float* __restrict__ A, int lda,
    const float* __restrict__ Bm, int ldb,
    int m0, int n0, int N, int K,
    float* sA, float* sB, unsigned long long acc[8][4])
{
    const int tid = threadIdx.x;
    const int tx = tid & 15, ty = tid >> 4;
#pragma unroll
    for (int i = 0; i < 8; i++)
#pragma unroll
        for (int p = 0; p < 4; p++) acc[i][p] = 0ULL;

    const int T = (K + 15) >> 4;
    const int idx0 = 2 * tid, idx1 = 2 * tid + 1;
    const int ma = idx0 >> 2, kqa = idx0 & 3;
    const int mb = idx1 >> 2, kqb = idx1 & 3;
    const float4 z4 = make_float4(0.f, 0.f, 0.f, 0.f);
    float4 ar0, ar1, br0, br1;

    // load tile 0
    {
        int gk0 = kqa * 4, gk1 = kqb * 4;
        ar0 = (gk0 < K) ? *(const float4*)(A + (size_t)(m0 + ma) * lda + gk0) : z4;
        ar1 = (gk1 < K) ? *(const float4*)(A + (size_t)(m0 + mb) * lda + gk1) : z4;
        br0 = (gk0 < K && n0 + ma < N) ? *(const float4*)(Bm + (size_t)(n0 + ma) * ldb + gk0) : z4;
        br1 = (gk1 < K && n0 + mb < N) ? *(const float4*)(Bm + (size_t)(n0 + mb) * ldb + gk1) : z4;
        sA[(kqa*4+0)*132+ma]=ar0.x; sA[(kqa*4+1)*132+ma]=ar0.y; sA[(kqa*4+2)*132+ma]=ar0.z; sA[(kqa*4+3)*132+ma]=ar0.w;
        sA[(kqb*4+0)*132+mb]=ar1.x; sA[(kqb*4+1)*132+mb]=ar1.y; sA[(kqb*4+2)*132+mb]=ar1.z; sA[(kqb*4+3)*132+mb]=ar1.w;
        sB[(kqa*4+0)*132+ma]=br0.x; sB[(kqa*4+1)*132+ma]=br0.y; sB[(kqa*4+2)*132+ma]=br0.z; sB[(kqa*4+3)*132+ma]=br0.w;
        sB[(kqb*4+0)*132+mb]=br1.x; sB[(kqb*4+1)*132+mb]=br1.y; sB[(kqb*4+2)*132+mb]=br1.z; sB[(kqb*4+3)*132+mb]=br1.w;
    }

    for (int t = 0; t < T; t++) {
        __syncthreads();
        if (t + 1 < T) {
            int k0 = (t + 1) << 4;
            int gk0 = k0 + kqa * 4, gk1 = k0 + kqb * 4;
            ar0 = (gk0 < K) ? *(const float4*)(A + (size_t)(m0 + ma) * lda + gk0) : z4;
            ar1 = (gk1 < K) ? *(const float4*)(A + (size_t)(m0 + mb) * lda + gk1) : z4;
            br0 = (gk0 < K && n0 + ma < N) ? *(const float4*)(Bm + (size_t)(n0 + ma) * ldb + gk0) : z4;
            br1 = (gk1 < K && n0 + mb < N) ? *(const float4*)(Bm + (size_t)(n0 + mb) * ldb + gk1) : z4;
        }
        const float* pA = sA + (t & 1) * SMSTRIDE;
        const float* pB = sB + (t & 1) * SMSTRIDE;
#pragma unroll
        for (int kk = 0; kk < 16; kk++) {
            const float* rB = pB + kk * 132;
            unsigned long long b0 = *(const unsigned long long*)(rB + tx * 4);
            unsigned long long b1 = *(const unsigned long long*)(rB + tx * 4 + 2);
            unsigned long long b2 = *(const unsigned long long*)(rB + 64 + tx * 4);
            unsigned long long b3 = *(const unsigned long long*)(rB + 64 + tx * 4 + 2);
            const float* rA = pA + kk * 132;
#pragma unroll
            for (int i = 0; i < 8; i++) {
                float av = (i < 4) ? rA[ty * 4 + i] : rA[64 + ty * 4 + i - 4];
                unsigned long long aa = pack2(av);
                acc[i][0] = ffma2(aa, b0, acc[i][0]);
                acc[i][1] = ffma2(aa, b1, acc[i][1]);
                acc[i][2] = ffma2(aa, b2, acc[i][2]);
                acc[i][3] = ffma2(aa, b3, acc[i][3]);
            }
        }
        if (t + 1 < T) {
            float* qA = sA + ((t + 1) & 1) * SMSTRIDE;
            float* qB = sB + ((t + 1) & 1) * SMSTRIDE;
            qA[(kqa*4+0)*132+ma]=ar0.x; qA[(kqa*4+1)*132+ma]=ar0.y; qA[(kqa*4+2)*132+ma]=ar0.z; qA[(kqa*4+3)*132+ma]=ar0.w;
            qA[(kqb*4+0)*132+mb]=ar1.x; qA[(kqb*4+1)*132+mb]=ar1.y; qA[(kqb*4+2)*132+mb]=ar1.z; qA[(kqb*4+3)*132+mb]=ar1.w;
            qB[(kqa*4+0)*132+ma]=br0.x; qB[(kqa*4+1)*132+ma]=br0.y; qB[(kqa*4+2)*132+ma]=br0.z; qB[(kqa*4+3)*132+ma]=br0.w;
            qB[(kqb*4+0)*132+mb]=br1.x; qB[(kqb*4+1)*132+mb]=br1.y; qB[(kqb*4+2)*132+mb]=br1.z; qB[(kqb*4+3)*132+mb]=br1.w;
        }
    }
}

__device__ __forceinline__ int row_of(int i, int m0, int ty) {
    return m0 + ((i < 4) ? (ty * 4 + i) : (64 + ty * 4 + i - 4));
}

// ---------------- plain GEMM kernel (MLP): +bias, relu --------------------------
__global__ void __launch_bounds__(256, 2) sgemm_nt(
    const float* __restrict__ A, int lda,
    const float* __restrict__ Bm, int ldb,
    const float* __restrict__ bias,
    float* __restrict__ C, int ldc,
    int M, int N, int K, int relu)
{
    __shared__ __align__(16) float sA[2 * SMSTRIDE];
    __shared__ __align__(16) float sB[2 * SMSTRIDE];
    unsigned long long acc[8][4];
    const int m0 = blockIdx.x * 128, n0 = blockIdx.y * 128;
    gemm_core(A, lda, Bm, ldb, m0, n0, N, K, sA, sB, acc);
    const int tx = threadIdx.x & 15, ty = threadIdx.x >> 4;
#pragma unroll
    for (int i = 0; i < 8; i++) {
        int m = row_of(i, m0, ty);
#pragma unroll
        for (int p = 0; p < 4; p++) {
            float lo, hi; unpack2(acc[i][p], lo, hi);
            int n = n0 + ((p & 2) ? 64 : 0) + tx * 4 + ((p & 1) ? 2 : 0);
            if (n < N) {
                float v = lo;
                if (bias) v = __fadd_rn(v, bias[n]);
                if (relu) v = fmaxf(v, 0.f);
                C[(size_t)m * ldc + n] = v;
            }
            if (n + 1 < N) {
                float v = hi;
                if (bias) v = __fadd_rn(v, bias[n + 1]);
                if (relu) v = fmaxf(v, 0.f);
                C[(size_t)m * ldc + n + 1] = v;
            }
        }
    }
}

// ---------------- fused gates GEMM + LSTM cell epilogue -------------------------
__device__ __forceinline__ float dot5_fma(const float* s, const float* w) {
    float a = 0.f;
    a = __fmaf_rn(s[0], w[0], a);
    a = __fmaf_rn(s[1], w[1], a);
    a = __fmaf_rn(s[2], w[2], a);
    a = __fmaf_rn(s[3], w[3], a);
    a = __fmaf_rn(s[4], w[4], a);
    return a;
}

__device__ __forceinline__ void cell_apply(int is_ti, const float gv[4], const float* s5,
                                           const float w[4][5], const float* bi, const float* bh,
                                           float* cptr, float* hptr)
{
    float gt[4];
#pragma unroll
    for (int g = 0; g < 4; g++) {
        float d5 = is_ti ? 0.f : dot5_fma(s5, w[g]);
        gt[g] = __fadd_rn(__fadd_rn(__fadd_rn(d5, bi[g]), gv[g]), bh[g]);
    }
    float cold = *cptr;
    float m1 = __fmul_rn(xla_sigm(gt[1]), cold);
    float m2 = __fmul_rn(xla_sigm(gt[0]), xla_tanh(gt[2]));
    float c  = __fadd_rn(m1, m2);
    *cptr = c;
    *hptr = __fmul_rn(xla_sigm(gt[3]), xla_tanh(c));
}

__global__ void __launch_bounds__(256, 2) gates_kernel(
    const float* __restrict__ h_to_cur, const float* __restrict__ h_ti_cur,
    float* __restrict__ h_to_nxt, float* __restrict__ h_ti_nxt)
{
    __shared__ __align__(16) float sA[2 * SMSTRIDE];
    __shared__ __align__(16) float sB[2 * SMSTRIDE];
    unsigned long long acc[8][4];
    const int y = blockIdx.y;
    const int is_ti = (y >= 8);
    const float* A = is_ti ? h_ti_cur : h_to_cur;
    const int m0 = blockIdx.x * 128, n0 = y * 128;
    gemm_core(A, HIDDIM, g_Wg, HIDDIM, m0, n0, 2048, HIDDIM, sA, sB, acc);

    const int tx = threadIdx.x & 15, ty = threadIdx.x >> 4;
    const int jA = (y & 7) * 32 + tx;        // cell index for pairs p=0,1
    const int jB = jA + 16;                  // cell index for pairs p=2,3
    const int nA = n0 + tx * 4;              // global weight rows of jA's gates
    const int nB = n0 + 64 + tx * 4;

    float biA[4], bhA[4], biB[4], bhB[4];
#pragma unroll
    for (int g = 0; g < 4; g++) {
        biA[g] = g_bihp[nA + g]; bhA[g] = g_bhhp[nA + g];
        biB[g] = g_bihp[nB + g]; bhB[g] = g_bhhp[nB + g];
    }
    float wA[4][5], wB[4][5];
    if (!is_ti) {
#pragma unroll
        for (int g = 0; g < 4; g++)
#pragma unroll
            for (int r = 0; r < 5; r++) {
                wA[g][r] = g_Wihp[(nA + g) * 5 + r];
                wB[g][r] = g_Wihp[(nB + g) * 5 + r];
            }
    }
    float* cbuf = is_ti ? g_c_ti : g_c_to;
    float* hn   = is_ti ? h_ti_nxt : h_to_nxt;

#pragma unroll
    for (int i = 0; i < 8; i++) {
        int m = row_of(i, m0, ty);
        float s5[5];
        if (!is_ti) {
#pragma unroll
            for (int r = 0; r < 5; r++) s5[r] = g_inp[m * 8 + r];
        }
        float ga[4], gb[4];
        unpack2(acc[i][0], ga[0], ga[1]); unpack2(acc[i][1], ga[2], ga[3]);
        unpack2(acc[i][2], gb[0], gb[1]); unpack2(acc[i][3], gb[2], gb[3]);
        cell_apply(is_ti, ga, s5, wA, biA, bhA, cbuf + (size_t)m * HIDDIM + jA, hn + (size_t)m * HIDDIM + jA);
        cell_apply(is_ti, gb, s5, wB, biB, bhB, cbuf + (size_t)m * HIDDIM + jB, hn + (size_t)m * HIDDIM + jB);
    }
}

// ---------------- fused logits GEMM (lto 4 tiles + lti 1 tile) ------------------
__global__ void __launch_bounds__(256, 2) logits_kernel(
    const float* __restrict__ h_to_nxt, const float* __restrict__ h_ti_nxt,
    const float* __restrict__ Wb, const float* __restrict__ bb)
{
    __shared__ __align__(16) float sA[2 * SMSTRIDE];
    __shared__ __align__(16) float sB[2 * SMSTRIDE];
    unsigned long long acc[8][4];
    const int y = blockIdx.y;
    const float *A, *B, *bias; float* C; int N, ldc, n0;
    if (y < 4) { A = h_to_nxt; B = g_WbWs; bias = g_bf; C = g_lto; N = NFUSE; ldc = NFUSE; n0 = y * 128; }
    else       { A = h_ti_nxt; B = Wb;     bias = bb;   C = g_lti; N = NBLOCK; ldc = NBLOCK; n0 = 0; }
    const int m0 = blockIdx.x * 128;
    gemm_core(A, HIDDIM, B, HIDDIM, m0, n0, N, HIDDIM, sA, sB, acc);
    const int tx = threadIdx.x & 15, ty = threadIdx.x >> 4;
#pragma unroll
    for (int i = 0; i < 8; i++) {
        int m = row_of(i, m0, ty);
#pragma unroll
        for (int p = 0; p < 4; p++) {
            float lo, hi; unpack2(acc[i][p], lo, hi);
            int n = n0 + ((p & 2) ? 64 : 0) + tx * 4 + ((p & 1) ? 2 : 0);
            if (n < N)     C[(size_t)m * ldc + n]     = __fadd_rn(lo, bias[n]);
            if (n + 1 < N) C[(size_t)m * ldc + n + 1] = __fadd_rn(hi, bias[n + 1]);
        }
    }
}

// ---------------- feat_vec + carry init ----------------
__global__ void feat_init_kernel(const float* __restrict__ W_fe2, const float* __restrict__ b_fe2,
                                 const float* __restrict__ to_t, const float* __restrict__ ti_t,
                                 const float* __restrict__ slot_info)
{
    int b = blockIdx.x, j = threadIdx.x;
    float f = 0.f;
#pragma unroll
    for (int r = 0; r < 5; r++)
        f = __fmaf_rn(g_act3[(size_t)(b * 5 + r) * HIDDIM + j], W_fe2[r], f);
    f = __fadd_rn(f, b_fe2[0]);
    g_h_to[0][b * HIDDIM + j] = f;
    g_h_ti[0][b * HIDDIM + j] = f;
    g_c_to[b * HIDDIM + j] = 0.f;
    g_c_ti[b * HIDDIM + j] = 0.f;
    if (j < 8) g_inp[b * 8 + j] = 0.f;
    if (j < NBLOCK) {
        g_mto[b * NBLOCK + j] = (to_t[((size_t)b * NBLOCK + j) * 5] != -1.0f);
        g_mti[b * NBLOCK + j] = (ti_t[((size_t)b * NBLOCK + j) * 5] != -1.0f);
    }
    for (int t = j; t < NSLOT * 5; t += HIDDIM)
        g_slots[(size_t)b * NSLOT * 5 + t] = slot_info[(size_t)b * NSLOT * 5 + t];
}

// ---------------- warp-per-batch masked argmax + state mutation -----------------
__global__ void select_kernel(const float* __restrict__ to_t, float* __restrict__ out_act, int step)
{
    const int w = threadIdx.x >> 5, l = threadIdx.x & 31;
    const int b = blockIdx.x * 4 + w;

    // ---- phase 1: block argmax (h_to logits) ----
    float v = -3.4e38f; int bi = 0x7fffffff;
    for (int i = l; i < NBLOCK; i += 32) {
        float lv = g_mto[b * NBLOCK + i] ? g_lto[(size_t)b * NFUSE + i] : NEGV;
        if (lv > v || (lv == v && i < bi)) { v = lv; bi = i; }
    }
#pragma unroll
    for (int o = 16; o; o >>= 1) {
        float v2 = __shfl_xor_sync(0xffffffffu, v, o);
        int   i2 = __shfl_xor_sync(0xffffffffu, bi, o);
        if (v2 > v || (v2 == v && i2 < bi)) { v = v2; bi = i2; }
    }
    const int sel_b = bi;
    if (l == 0) {
        g_mto[b * NBLOCK + sel_b] = 0;
#pragma unroll
        for (int r = 0; r < 5; r++)
            g_inp[b * 8 + r] = to_t[((size_t)b * NBLOCK + sel_b) * 5 + r];
    }
    const float bl0 = to_t[((size_t)b * NBLOCK + sel_b) * 5 + 0];
    const float bl1 = to_t[((size_t)b * NBLOCK + sel_b) * 5 + 1];

    // ---- phase 2: slot argmax ----
    v = -3.4e38f; bi = 0x7fffffff;
    for (int i = l; i < NSLOT; i += 32) {
        const float* sl = g_slots + ((size_t)b * NSLOT + i) * 5;
        float l0 = sl[0], w0 = sl[1];
        bool bad = (bl0 >= l0) || (bl1 >= w0) || (l0 == 0.0f);
        float lv = bad ? NEGV : g_lto[(size_t)b * NFUSE + NBLOCK + i];
        if (lv > v || (lv == v && i < bi)) { v = lv; bi = i; }
    }
#pragma unroll
    for (int o = 16; o; o >>= 1) {
        float v2 = __shfl_xor_sync(0xffffffffu, v, o);
        int   i2 = __shfl_xor_sync(0xffffffffu, bi, o);
        if (v2 > v || (v2 == v && i2 < bi)) { v = v2; bi = i2; }
    }
    const int sel_s = bi;
    if (l == 0) {
        float* sl = g_slots + ((size_t)b * NSLOT + sel_s) * 5;
        float cnt = __fadd_rn(sl[4], -1.0f);
        sl[4] = cnt;
        if (cnt == 0.0f) { sl[0] = 0.f; sl[1] = 0.f; sl[2] = 0.f; sl[3] = 0.f; sl[4] = 0.f; }
    }

    // ---- phase 3: ti block argmax (h_ti logits) ----
    v = -3.4e38f; bi = 0x7fffffff;
    for (int i = l; i < NBLOCK; i += 32) {
        float lv = g_mti[b * NBLOCK + i] ? g_lti[(size_t)b * NBLOCK + i] : NEGV;
        if (lv > v || (lv == v && i < bi)) { v = lv; bi = i; }
    }
#pragma unroll
    for (int o = 16; o; o >>= 1) {
        float v2 = __shfl_xor_sync(0xffffffffu, v, o);
        int   i2 = __shfl_xor_sync(0xffffffffu, bi, o);
        if (v2 > v || (v2 == v && i2 < bi)) { v = v2; bi = i2; }
    }
    if (l == 0) {
        g_mti[b * NBLOCK + bi] = 0;
        float* oa = out_act + ((size_t)b * NSTEPS + step) * 3;
        oa[0] = (float)sel_b;
        oa[1] = (float)sel_s;
        oa[2] = (float)bi;
    }
}

// ---------------- launch ----------------
extern "C" void kernel_launch(void* const* d_in, const int* in_sizes, int n_in,
                              void* d_out, int out_size)
{
    const float* to_t    = (const float*)d_in[0];
    const float* ti_t    = (const float*)d_in[1];
    const float* ys_t    = (const float*)d_in[2];
    const float* slot    = (const float*)d_in[3];
    const float* W1      = (const float*)d_in[4];
    const float* b1      = (const float*)d_in[5];
    const float* W2      = (const float*)d_in[6];
    const float* b2      = (const float*)d_in[7];
    const float* W3      = (const float*)d_in[8];
    const float* b3      = (const float*)d_in[9];
    const float* W_fe2   = (const float*)d_in[10];
    const float* b_fe2   = (const float*)d_in[11];
    const float* Wih_to  = (const float*)d_in[12];
    const float* Whh_to  = (const float*)d_in[13];
    const float* bih_to  = (const float*)d_in[14];
    const float* bhh_to  = (const float*)d_in[15];
    const float* Whh_ti  = (const float*)d_in[17];
    const float* bih_ti  = (const float*)d_in[18];
    const float* bhh_ti  = (const float*)d_in[19];
    const float* Wb      = (const float*)d_in[20];
    const float* bb      = (const float*)d_in[21];
    const float* Ws      = (const float*)d_in[22];
    const float* bs      = (const float*)d_in[23];

    float* out     = (float*)d_out;
    float* out_act = out + (size_t)BATCH * KST * 5;

    float *p_xT, *p_a1, *p_a2, *p_a3, *p_hto, *p_hti;
    cudaGetSymbolAddress((void**)&p_xT,  g_xT);
    cudaGetSymbolAddress((void**)&p_a1,  g_act1);
    cudaGetSymbolAddress((void**)&p_a2,  g_act2);
    cudaGetSymbolAddress((void**)&p_a3,  g_act3);
    cudaGetSymbolAddress((void**)&p_hto, g_h_to);
    cudaGetSymbolAddress((void**)&p_hti, g_h_ti);
    float* h_to_buf[2] = { p_hto, p_hto + BATCH * HIDDIM };
    float* h_ti_buf[2] = { p_hti, p_hti + BATCH * HIDDIM };

    // prep: state copy + transposed MLP input + permuted weights
    int nprep = (BATCH * KST + 255) / 256;
    prep_kernel<<<nprep, 256>>>(to_t, ti_t, ys_t, out);
    prep_weights<<<2048, 256>>>(Whh_to, Whh_ti, bih_to, bhh_to, bih_ti, bhh_ti,
                                Wih_to, Wb, bb, Ws, bs);

    // MLP (relu fused, bias fused)
    dim3 g1(M5 / 128, 512 / 128);
    sgemm_nt<<<g1, 256>>>(p_xT, KST, W1, KST, b1, p_a1, 512, M5, 512, KST, 1);
    sgemm_nt<<<g1, 256>>>(p_a1, 512, W2, 512, b2, p_a2, 512, M5, 512, 512, 1);
    dim3 g3(M5 / 128, 256 / 128);
    sgemm_nt<<<g3, 256>>>(p_a2, 512, W3, 512, b3, p_a3, 256, M5, 256, 512, 1);
    feat_init_kernel<<<BATCH, HIDDIM>>>(W_fe2, b_fe2, to_t, ti_t, slot);

    dim3 gg(BATCH / 128, 16);
    dim3 gl(BATCH / 128, 5);
    for (int s = 0; s < NSTEPS; s++) {
        int cur = s & 1, nxt = cur ^ 1;
        gates_kernel <<<gg, 256>>>(h_to_buf[cur], h_ti_buf[cur], h_to_buf[nxt], h_ti_buf[nxt]);
        logits_kernel<<<gl, 256>>>(h_to_buf[nxt], h_ti_buf[nxt], Wb, bb);
        select_kernel<<<BATCH / 4, 128>>>(to_t, out_act, s);
    }
}